// round 6
// baseline (speedup 1.0000x reference)
#include <cuda_runtime.h>
#include <cuda_bf16.h>
#include <cstdint>

// Problem constants
#define BB 2
#define LL 4096
#define CC 512
#define HH 8
#define KK 13
#define DH 64
#define RR 6              // K/2
#define NBIAS 25          // 2K-1
#define SCALE 0.125f      // DH^-0.5

#define M_TOTAL (BB * LL)   // 8192 rows per GEMM

// GEMM tiling: 128x128 tile, BK=32, 3-stage cp.async
#define BKD 32
#define AS_STRIDE 36        // 32 k + 4 pad; 144B row (16B aligned); banks 4g+t
#define BS_STRIDE 136       // 128 n + 8 pad; 544B row (16B aligned); banks 8t+g
#define STAGES 3
#define A_STAGE (128 * AS_STRIDE)    // 4608 floats
#define B_STAGE (BKD * BS_STRIDE)    // 4352 floats
#define SMEM_FLOATS (STAGES * (A_STAGE + B_STAGE))   // 26880 -> 107520 B

// ---------------------------------------------------------------------------
// Scratch (no cudaMalloc allowed)
// ---------------------------------------------------------------------------
__device__ float g_qh[M_TOTAL * CC];
__device__ float g_kh[M_TOTAL * CC];
__device__ float g_vh[M_TOTAL * CC];
__device__ float g_att[M_TOTAL * CC];
__device__ float g_rw[4][CC * CC];   // RNA-tf32-rounded weights

// ---------------------------------------------------------------------------
// Helpers
// ---------------------------------------------------------------------------
__device__ __forceinline__ uint32_t f2tf32(float x) {
    uint32_t r;
    asm("cvt.rna.tf32.f32 %0, %1;" : "=r"(r) : "f"(x));
    return r;
}

__device__ __forceinline__ void mma_tf32(float& c0, float& c1, float& c2, float& c3,
                                         uint32_t a0, uint32_t a1, uint32_t a2, uint32_t a3,
                                         uint32_t b0, uint32_t b1) {
    asm volatile(
        "mma.sync.aligned.m16n8k8.row.col.f32.tf32.tf32.f32 "
        "{%0,%1,%2,%3}, {%4,%5,%6,%7}, {%8,%9}, {%0,%1,%2,%3};"
        : "+f"(c0), "+f"(c1), "+f"(c2), "+f"(c3)
        : "r"(a0), "r"(a1), "r"(a2), "r"(a3), "r"(b0), "r"(b1));
}

__device__ __forceinline__ void cp_async16(uint32_t smem_addr, const void* gptr) {
    asm volatile("cp.async.cg.shared.global [%0], [%1], 16;"
                 :: "r"(smem_addr), "l"(gptr));
}
__device__ __forceinline__ void cp_commit() {
    asm volatile("cp.async.commit_group;");
}
template <int N>
__device__ __forceinline__ void cp_wait() {
    asm volatile("cp.async.wait_group %0;" :: "n"(N));
}

// ---------------------------------------------------------------------------
// Elementwise RNA tf32 rounding (for weights, done once per launch)
// ---------------------------------------------------------------------------
__global__ void round_tf32(const float* __restrict__ in, float* __restrict__ out)
{
    const int idx = (blockIdx.x * 256 + threadIdx.x) * 4;
    const float4 a = *reinterpret_cast<const float4*>(in + idx);
    float4 o;
    o.x = __uint_as_float(f2tf32(a.x));
    o.y = __uint_as_float(f2tf32(a.y));
    o.z = __uint_as_float(f2tf32(a.z));
    o.w = __uint_as_float(f2tf32(a.w));
    *reinterpret_cast<float4*>(out + idx) = o;
}

// ---------------------------------------------------------------------------
// TF32 tensor-core GEMM body. C[M,512] = A[M,512] @ W[512,512] + bias
// Block tile 128x128, BK=32, 256 threads (8 warps, 2x4), warp tile 64x32.
// CVT_A: convert A fragments to tf32 at load (false if A is pre-rounded).
// B (weights) is always pre-rounded -> loaded raw.
// ---------------------------------------------------------------------------
template <bool CVT_A>
__device__ __forceinline__
void gemm_body(const float* __restrict__ A,
               const float* __restrict__ W,
               const float* __restrict__ bias,
               float* __restrict__ C)
{
    extern __shared__ float smem[];
    float* As = smem;
    float* Bs = smem + STAGES * A_STAGE;

    const uint32_t as_base = (uint32_t)__cvta_generic_to_shared(As);
    const uint32_t bs_base = (uint32_t)__cvta_generic_to_shared(Bs);

    const int tid  = threadIdx.x;
    const int warp = tid >> 5;
    const int lane = tid & 31;
    const int g = lane >> 2;
    const int t = lane & 3;
    const int wm = (warp & 1) * 64;
    const int wn = (warp >> 1) * 32;
    const int block_row = blockIdx.y * 128;
    const int block_col = blockIdx.x * 128;

    const float* Abase = A + (size_t)block_row * CC;
    const float* Wbase = W + block_col;

    const int NT = CC / BKD;   // 16 K-tiles

    // Per-tile copy: A = 128x32 = 1024 f4, B = 32x128 = 1024 f4; 4 each/thread.
    auto issue_tile = [&](int it, int stg) {
        const float* An = Abase + it * BKD;
        const float* Wn = Wbase + (size_t)it * BKD * CC;
        const uint32_t a_off = as_base + (uint32_t)stg * (A_STAGE * 4u);
        const uint32_t b_off = bs_base + (uint32_t)stg * (B_STAGE * 4u);
#pragma unroll
        for (int i = 0; i < 4; i++) {
            const int idx = tid + i * 256;
            const int ar = idx >> 3, akq = (idx & 7) * 4;      // row 0..127, col 0..28
            cp_async16(a_off + (uint32_t)(ar * AS_STRIDE + akq) * 4u,
                       An + (size_t)ar * CC + akq);
            const int br = idx >> 5, bcq = (idx & 31) * 4;     // krow 0..31, col 0..124
            cp_async16(b_off + (uint32_t)(br * BS_STRIDE + bcq) * 4u,
                       Wn + (size_t)br * CC + bcq);
        }
        cp_commit();
    };

    float acc[4][4][4];
#pragma unroll
    for (int mi = 0; mi < 4; mi++)
#pragma unroll
        for (int ni = 0; ni < 4; ni++)
#pragma unroll
            for (int r = 0; r < 4; r++) acc[mi][ni][r] = 0.0f;

    issue_tile(0, 0);
    issue_tile(1, 1);
    cp_wait<1>();
    __syncthreads();

    int cur = 0;
    for (int it = 0; it < NT; ++it) {
        if (it + 2 < NT) issue_tile(it + 2, (cur + 2) % STAGES);

        const float* asf = As + cur * A_STAGE;
        const float* bsf = Bs + cur * B_STAGE;
        const uint32_t* bsu = reinterpret_cast<const uint32_t*>(bsf);
#pragma unroll
        for (int k0 = 0; k0 < BKD; k0 += 8) {
            uint32_t ar[4][4], br[4][2];
#pragma unroll
            for (int mi = 0; mi < 4; mi++) {
                const int r0 = (wm + mi * 16 + g) * AS_STRIDE;
                const int r8 = r0 + 8 * AS_STRIDE;
                if (CVT_A) {
                    ar[mi][0] = f2tf32(asf[r0 + k0 + t]);
                    ar[mi][1] = f2tf32(asf[r8 + k0 + t]);
                    ar[mi][2] = f2tf32(asf[r0 + k0 + t + 4]);
                    ar[mi][3] = f2tf32(asf[r8 + k0 + t + 4]);
                } else {
                    const uint32_t* asu = reinterpret_cast<const uint32_t*>(asf);
                    ar[mi][0] = asu[r0 + k0 + t];
                    ar[mi][1] = asu[r8 + k0 + t];
                    ar[mi][2] = asu[r0 + k0 + t + 4];
                    ar[mi][3] = asu[r8 + k0 + t + 4];
                }
            }
#pragma unroll
            for (int ni = 0; ni < 4; ni++) {
                const int c0 = wn + ni * 8 + g;
                br[ni][0] = bsu[(k0 + t) * BS_STRIDE + c0];
                br[ni][1] = bsu[(k0 + t + 4) * BS_STRIDE + c0];
            }
#pragma unroll
            for (int mi = 0; mi < 4; mi++)
#pragma unroll
                for (int ni = 0; ni < 4; ni++)
                    mma_tf32(acc[mi][ni][0], acc[mi][ni][1], acc[mi][ni][2], acc[mi][ni][3],
                             ar[mi][0], ar[mi][1], ar[mi][2], ar[mi][3],
                             br[ni][0], br[ni][1]);
        }

        cp_wait<1>();
        __syncthreads();
        cur = (cur + 1) % STAGES;
    }

#pragma unroll
    for (int mi = 0; mi < 4; mi++) {
        const int row0 = block_row + wm + mi * 16 + g;
#pragma unroll
        for (int ni = 0; ni < 4; ni++) {
            const int col0 = block_col + wn + ni * 8 + t * 2;
            const float2 b2 = *reinterpret_cast<const float2*>(bias + col0);
            float2 o;
            o.x = acc[mi][ni][0] + b2.x;
            o.y = acc[mi][ni][1] + b2.y;
            *reinterpret_cast<float2*>(C + (size_t)row0 * CC + col0) = o;
            o.x = acc[mi][ni][2] + b2.x;
            o.y = acc[mi][ni][3] + b2.y;
            *reinterpret_cast<float2*>(C + (size_t)(row0 + 8) * CC + col0) = o;
        }
    }
}

// Batched QKV: blockIdx.z selects (A, W, bias, C); A needs cvt
__global__ __launch_bounds__(256, 2)
void tf32_gemm_qkv(const float* __restrict__ q, const float* __restrict__ k,
                   const float* __restrict__ v,
                   const float* __restrict__ Wq, const float* __restrict__ Wk,
                   const float* __restrict__ Wv,
                   const float* __restrict__ bq, const float* __restrict__ bk,
                   const float* __restrict__ bv,
                   float* __restrict__ qh, float* __restrict__ kh,
                   float* __restrict__ vh)
{
    const int z = blockIdx.z;
    const float* A    = (z == 0) ? q  : (z == 1) ? k  : v;
    const float* W    = (z == 0) ? Wq : (z == 1) ? Wk : Wv;
    const float* bias = (z == 0) ? bq : (z == 1) ? bk : bv;
    float*       C    = (z == 0) ? qh : (z == 1) ? kh : vh;
    gemm_body<true>(A, W, bias, C);
}

// Output GEMM: A (att) is pre-rounded by natt -> no cvt anywhere
__global__ __launch_bounds__(256, 2)
void tf32_gemm_out(const float* __restrict__ A, const float* __restrict__ W,
                   const float* __restrict__ bias, float* __restrict__ C)
{
    gemm_body<false>(A, W, bias, C);
}

// ---------------------------------------------------------------------------
// Neighborhood attention, vectorized; writes tf32-rounded output.
// Lane layout: qi = lane>>3 (4 queries/warp), d8 = (lane&7)*8.
// ---------------------------------------------------------------------------
__global__ __launch_bounds__(256)
void natt_kernel(const float* __restrict__ qh,
                 const float* __restrict__ kh,
                 const float* __restrict__ vh,
                 const float* __restrict__ rpb,
                 float* __restrict__ out)
{
    const int bi0  = blockIdx.x * 4;
    const int h    = threadIdx.x >> 5;
    const int lane = threadIdx.x & 31;
    const int qi   = lane >> 3;
    const int d8   = (lane & 7) * 8;

    const int bi = bi0 + qi;
    const int i  = bi & (LL - 1);

    int start = i - RR;
    if (start < 0) start = 0;
    if (start > LL - KK) start = LL - KK;

    const size_t qoff = (size_t)bi * CC + h * DH + d8;
    float4 qa = *reinterpret_cast<const float4*>(qh + qoff);
    float4 qb = *reinterpret_cast<const float4*>(qh + qoff + 4);
    qa.x *= SCALE; qa.y *= SCALE; qa.z *= SCALE; qa.w *= SCALE;
    qb.x *= SCALE; qb.y *= SCALE; qb.z *= SCALE; qb.w *= SCALE;

    const size_t nbase = (size_t)(bi - i + start) * CC + h * DH + d8;
    const int bias_off = h * NBIAS + (start - i + (KK - 1));

    float s[KK];
#pragma unroll
    for (int k = 0; k < KK; k++) {
        const float* kp = kh + nbase + (size_t)k * CC;
        const float4 ka = *reinterpret_cast<const float4*>(kp);
        const float4 kb = *reinterpret_cast<const float4*>(kp + 4);
        float d = qa.x * ka.x + qa.y * ka.y + qa.z * ka.z + qa.w * ka.w
                + qb.x * kb.x + qb.y * kb.y + qb.z * kb.z + qb.w * kb.w;
        d += __shfl_xor_sync(0xffffffffu, d, 1);
        d += __shfl_xor_sync(0xffffffffu, d, 2);
        d += __shfl_xor_sync(0xffffffffu, d, 4);
        s[k] = d + rpb[bias_off + k];
    }

    float m = s[0];
#pragma unroll
    for (int k = 1; k < KK; k++) m = fmaxf(m, s[k]);
    float sum = 0.0f;
#pragma unroll
    for (int k = 0; k < KK; k++) { s[k] = __expf(s[k] - m); sum += s[k]; }
    const float inv = 1.0f / sum;

    float4 oa = make_float4(0.f, 0.f, 0.f, 0.f);
    float4 ob = make_float4(0.f, 0.f, 0.f, 0.f);
#pragma unroll
    for (int k = 0; k < KK; k++) {
        const float* vp = vh + nbase + (size_t)k * CC;
        const float4 va = *reinterpret_cast<const float4*>(vp);
        const float4 vb = *reinterpret_cast<const float4*>(vp + 4);
        const float p = s[k] * inv;
        oa.x = fmaf(p, va.x, oa.x); oa.y = fmaf(p, va.y, oa.y);
        oa.z = fmaf(p, va.z, oa.z); oa.w = fmaf(p, va.w, oa.w);
        ob.x = fmaf(p, vb.x, ob.x); ob.y = fmaf(p, vb.y, ob.y);
        ob.z = fmaf(p, vb.z, ob.z); ob.w = fmaf(p, vb.w, ob.w);
    }

    // Round to tf32 so the output GEMM can skip A conversion
    float4 ra, rb;
    ra.x = __uint_as_float(f2tf32(oa.x)); ra.y = __uint_as_float(f2tf32(oa.y));
    ra.z = __uint_as_float(f2tf32(oa.z)); ra.w = __uint_as_float(f2tf32(oa.w));
    rb.x = __uint_as_float(f2tf32(ob.x)); rb.y = __uint_as_float(f2tf32(ob.y));
    rb.z = __uint_as_float(f2tf32(ob.z)); rb.w = __uint_as_float(f2tf32(ob.w));
    *reinterpret_cast<float4*>(out + qoff)     = ra;
    *reinterpret_cast<float4*>(out + qoff + 4) = rb;
}

// ---------------------------------------------------------------------------
// Launch. Inputs: q, k, v, Wq, bq, Wk, bk, Wv, bv, rpb, Wo, bo
// ---------------------------------------------------------------------------
extern "C" void kernel_launch(void* const* d_in, const int* in_sizes, int n_in,
                              void* d_out, int out_size)
{
    const float* q   = (const float*)d_in[0];
    const float* k   = (const float*)d_in[1];
    const float* v   = (const float*)d_in[2];
    const float* Wq  = (const float*)d_in[3];
    const float* bq  = (const float*)d_in[4];
    const float* Wk  = (const float*)d_in[5];
    const float* bk  = (const float*)d_in[6];
    const float* Wv  = (const float*)d_in[7];
    const float* bv  = (const float*)d_in[8];
    const float* rpb = (const float*)d_in[9];
    const float* Wo  = (const float*)d_in[10];
    const float* bo  = (const float*)d_in[11];
    float* out = (float*)d_out;

    float *qh, *kh, *vh, *att, *rw;
    cudaGetSymbolAddress((void**)&qh,  g_qh);
    cudaGetSymbolAddress((void**)&kh,  g_kh);
    cudaGetSymbolAddress((void**)&vh,  g_vh);
    cudaGetSymbolAddress((void**)&att, g_att);
    cudaGetSymbolAddress((void**)&rw,  g_rw);

    float* rwq = rw;
    float* rwk = rw + 1 * CC * CC;
    float* rwv = rw + 2 * CC * CC;
    float* rwo = rw + 3 * CC * CC;

    const int smem_bytes = SMEM_FLOATS * 4;   // 107520 B
    cudaFuncSetAttribute(tf32_gemm_qkv,
                         cudaFuncAttributeMaxDynamicSharedMemorySize, smem_bytes);
    cudaFuncSetAttribute(tf32_gemm_out,
                         cudaFuncAttributeMaxDynamicSharedMemorySize, smem_bytes);

    // Pre-round weights (CC*CC/1024 = 256 blocks)
    round_tf32<<<CC * CC / 1024, 256>>>(Wq, rwq);
    round_tf32<<<CC * CC / 1024, 256>>>(Wk, rwk);
    round_tf32<<<CC * CC / 1024, 256>>>(Wv, rwv);
    round_tf32<<<CC * CC / 1024, 256>>>(Wo, rwo);

    dim3 qkv_grid(CC / 128, M_TOTAL / 128, 3);   // (4, 64, 3)
    tf32_gemm_qkv<<<qkv_grid, 256, smem_bytes>>>(q, k, v, rwq, rwk, rwv,
                                                 bq, bk, bv, qh, kh, vh);

    natt_kernel<<<M_TOTAL / 4, 256>>>(qh, kh, vh, rpb, att);

    dim3 gemm_grid(CC / 128, M_TOTAL / 128);     // (4, 64)
    tf32_gemm_out<<<gemm_grid, 256, smem_bytes>>>(att, rwo, bo, out);
}

// round 7
// speedup vs baseline: 1.0295x; 1.0295x over previous
#include <cuda_runtime.h>
#include <cuda_bf16.h>
#include <cstdint>

// Problem constants
#define BB 2
#define LL 4096
#define CC 512
#define HH 8
#define KK 13
#define DH 64
#define RR 6              // K/2
#define NBIAS 25          // 2K-1
#define SCALE 0.125f      // DH^-0.5

#define M_TOTAL (BB * LL)   // 8192 rows per GEMM

// GEMM tiling: 128x128 tile, BK=32, 3-stage cp.async, 512 threads (16 warps 4x4)
#define BKD 32
#define AS_STRIDE 36        // 32 k + 4 pad; banks 4g+t distinct
#define BS_STRIDE 136       // 128 n + 8 pad; banks 8t+g distinct
#define STAGES 3
#define A_STAGE (128 * AS_STRIDE)    // 4608 floats
#define B_STAGE (BKD * BS_STRIDE)    // 4352 floats
#define SMEM_FLOATS (STAGES * (A_STAGE + B_STAGE))   // 26880 -> 107520 B

// ---------------------------------------------------------------------------
// Scratch (no cudaMalloc allowed)
// ---------------------------------------------------------------------------
__device__ float g_qh[M_TOTAL * CC];
__device__ float g_kh[M_TOTAL * CC];
__device__ float g_vh[M_TOTAL * CC];
__device__ float g_att[M_TOTAL * CC];
__device__ float g_rw[4][CC * CC];   // RNA-tf32-rounded weights

// ---------------------------------------------------------------------------
// Helpers
// ---------------------------------------------------------------------------
__device__ __forceinline__ uint32_t f2tf32(float x) {
    uint32_t r;
    asm("cvt.rna.tf32.f32 %0, %1;" : "=r"(r) : "f"(x));
    return r;
}

__device__ __forceinline__ void mma_tf32(float& c0, float& c1, float& c2, float& c3,
                                         uint32_t a0, uint32_t a1, uint32_t a2, uint32_t a3,
                                         uint32_t b0, uint32_t b1) {
    asm volatile(
        "mma.sync.aligned.m16n8k8.row.col.f32.tf32.tf32.f32 "
        "{%0,%1,%2,%3}, {%4,%5,%6,%7}, {%8,%9}, {%0,%1,%2,%3};"
        : "+f"(c0), "+f"(c1), "+f"(c2), "+f"(c3)
        : "r"(a0), "r"(a1), "r"(a2), "r"(a3), "r"(b0), "r"(b1));
}

__device__ __forceinline__ void cp_async16(uint32_t smem_addr, const void* gptr) {
    asm volatile("cp.async.cg.shared.global [%0], [%1], 16;"
                 :: "r"(smem_addr), "l"(gptr));
}
__device__ __forceinline__ void cp_commit() {
    asm volatile("cp.async.commit_group;");
}
template <int N>
__device__ __forceinline__ void cp_wait() {
    asm volatile("cp.async.wait_group %0;" :: "n"(N));
}

// ---------------------------------------------------------------------------
// Weight rounding: ONE launch for all 4 weights (blockIdx.y selects matrix)
// ---------------------------------------------------------------------------
__global__ void round_tf32_all(const float* __restrict__ w0, const float* __restrict__ w1,
                               const float* __restrict__ w2, const float* __restrict__ w3,
                               float* __restrict__ o)
{
    const float* w = (blockIdx.y == 0) ? w0 : (blockIdx.y == 1) ? w1
                   : (blockIdx.y == 2) ? w2 : w3;
    float* dst = o + (size_t)blockIdx.y * CC * CC;
    const int idx = (blockIdx.x * 256 + threadIdx.x) * 4;
    const float4 a = *reinterpret_cast<const float4*>(w + idx);
    float4 r;
    r.x = __uint_as_float(f2tf32(a.x));
    r.y = __uint_as_float(f2tf32(a.y));
    r.z = __uint_as_float(f2tf32(a.z));
    r.w = __uint_as_float(f2tf32(a.w));
    *reinterpret_cast<float4*>(dst + idx) = r;
}

// ---------------------------------------------------------------------------
// TF32 tensor-core GEMM body. C[M,512] = A[M,512] @ W[512,512] + bias
// 512 threads, 16 warps (4x4), warp tile 32x32, BK=32, 3-stage cp.async.
// B is pre-rounded -> loaded raw. CVT_A selects A-fragment conversion.
// ---------------------------------------------------------------------------
template <bool CVT_A>
__device__ __forceinline__
void gemm_body(const float* __restrict__ A,
               const float* __restrict__ W,
               const float* __restrict__ bias,
               float* __restrict__ C)
{
    extern __shared__ float smem[];
    float* As = smem;
    float* Bs = smem + STAGES * A_STAGE;

    const uint32_t as_base = (uint32_t)__cvta_generic_to_shared(As);
    const uint32_t bs_base = (uint32_t)__cvta_generic_to_shared(Bs);

    const int tid  = threadIdx.x;
    const int warp = tid >> 5;        // 0..15
    const int lane = tid & 31;
    const int g = lane >> 2;          // 0..7
    const int t = lane & 3;           // 0..3
    const int wm = (warp >> 2) * 32;  // warp m offset (4 rows of warps)
    const int wn = (warp & 3) * 32;   // warp n offset (4 cols of warps)
    const int block_row = blockIdx.y * 128;
    const int block_col = blockIdx.x * 128;

    const float* Abase = A + (size_t)block_row * CC;
    const float* Wbase = W + block_col;

    const int NT = CC / BKD;   // 16 K-tiles

    // Per-tile copy: A = 1024 float4, B = 1024 float4; 2 each per thread.
    auto issue_tile = [&](int it, int stg) {
        const float* An = Abase + it * BKD;
        const float* Wn = Wbase + (size_t)it * BKD * CC;
        const uint32_t a_off = as_base + (uint32_t)stg * (A_STAGE * 4u);
        const uint32_t b_off = bs_base + (uint32_t)stg * (B_STAGE * 4u);
#pragma unroll
        for (int i = 0; i < 2; i++) {
            const int idx = tid + i * 512;
            const int arow = idx >> 3, akq = (idx & 7) * 4;
            cp_async16(a_off + (uint32_t)(arow * AS_STRIDE + akq) * 4u,
                       An + (size_t)arow * CC + akq);
            const int brow = idx >> 5, bcq = (idx & 31) * 4;
            cp_async16(b_off + (uint32_t)(brow * BS_STRIDE + bcq) * 4u,
                       Wn + (size_t)brow * CC + bcq);
        }
        cp_commit();
    };

    float acc[2][4][4];
#pragma unroll
    for (int mi = 0; mi < 2; mi++)
#pragma unroll
        for (int ni = 0; ni < 4; ni++)
#pragma unroll
            for (int r = 0; r < 4; r++) acc[mi][ni][r] = 0.0f;

    issue_tile(0, 0);
    issue_tile(1, 1);
    cp_wait<1>();
    __syncthreads();

    int cur = 0;
    for (int it = 0; it < NT; ++it) {
        if (it + 2 < NT) issue_tile(it + 2, (cur + 2) % STAGES);

        const float* asf = As + cur * A_STAGE;
        const uint32_t* asu = reinterpret_cast<const uint32_t*>(asf);
        const uint32_t* bsu = reinterpret_cast<const uint32_t*>(Bs + cur * B_STAGE);
#pragma unroll
        for (int k0 = 0; k0 < BKD; k0 += 8) {
            uint32_t ar[2][4], br[4][2];
#pragma unroll
            for (int mi = 0; mi < 2; mi++) {
                const int r0 = (wm + mi * 16 + g) * AS_STRIDE;
                const int r8 = r0 + 8 * AS_STRIDE;
                if (CVT_A) {
                    ar[mi][0] = f2tf32(asf[r0 + k0 + t]);
                    ar[mi][1] = f2tf32(asf[r8 + k0 + t]);
                    ar[mi][2] = f2tf32(asf[r0 + k0 + t + 4]);
                    ar[mi][3] = f2tf32(asf[r8 + k0 + t + 4]);
                } else {
                    ar[mi][0] = asu[r0 + k0 + t];
                    ar[mi][1] = asu[r8 + k0 + t];
                    ar[mi][2] = asu[r0 + k0 + t + 4];
                    ar[mi][3] = asu[r8 + k0 + t + 4];
                }
            }
#pragma unroll
            for (int ni = 0; ni < 4; ni++) {
                const int c0 = wn + ni * 8 + g;
                br[ni][0] = bsu[(k0 + t) * BS_STRIDE + c0];
                br[ni][1] = bsu[(k0 + t + 4) * BS_STRIDE + c0];
            }
#pragma unroll
            for (int mi = 0; mi < 2; mi++)
#pragma unroll
                for (int ni = 0; ni < 4; ni++)
                    mma_tf32(acc[mi][ni][0], acc[mi][ni][1], acc[mi][ni][2], acc[mi][ni][3],
                             ar[mi][0], ar[mi][1], ar[mi][2], ar[mi][3],
                             br[ni][0], br[ni][1]);
        }

        cp_wait<1>();
        __syncthreads();
        cur = (cur + 1) % STAGES;
    }

    // Epilogue
#pragma unroll
    for (int mi = 0; mi < 2; mi++) {
        const int row0 = block_row + wm + mi * 16 + g;
#pragma unroll
        for (int ni = 0; ni < 4; ni++) {
            const int col0 = block_col + wn + ni * 8 + t * 2;
            const float2 b2 = *reinterpret_cast<const float2*>(bias + col0);
            float2 o;
            o.x = acc[mi][ni][0] + b2.x;
            o.y = acc[mi][ni][1] + b2.y;
            *reinterpret_cast<float2*>(C + (size_t)row0 * CC + col0) = o;
            o.x = acc[mi][ni][2] + b2.x;
            o.y = acc[mi][ni][3] + b2.y;
            *reinterpret_cast<float2*>(C + (size_t)(row0 + 8) * CC + col0) = o;
        }
    }
}

// Batched QKV: blockIdx.z selects (A, W, bias, C); A needs cvt
__global__ __launch_bounds__(512, 2)
void tf32_gemm_qkv(const float* __restrict__ q, const float* __restrict__ k,
                   const float* __restrict__ v,
                   const float* __restrict__ rw,
                   const float* __restrict__ bq, const float* __restrict__ bk,
                   const float* __restrict__ bv,
                   float* __restrict__ qh, float* __restrict__ kh,
                   float* __restrict__ vh)
{
    const int z = blockIdx.z;
    const float* A    = (z == 0) ? q  : (z == 1) ? k  : v;
    const float* W    = rw + (size_t)z * CC * CC;
    const float* bias = (z == 0) ? bq : (z == 1) ? bk : bv;
    float*       C    = (z == 0) ? qh : (z == 1) ? kh : vh;
    gemm_body<true>(A, W, bias, C);
}

// Output GEMM: A (att) pre-rounded by natt -> no cvt anywhere
__global__ __launch_bounds__(512, 2)
void tf32_gemm_out(const float* __restrict__ A, const float* __restrict__ W,
                   const float* __restrict__ bias, float* __restrict__ C)
{
    gemm_body<false>(A, W, bias, C);
}

// ---------------------------------------------------------------------------
// Neighborhood attention, vectorized; writes tf32-rounded output.
// Lane layout: qi = lane>>3 (4 queries/warp), d8 = (lane&7)*8.
// ---------------------------------------------------------------------------
__global__ __launch_bounds__(256)
void natt_kernel(const float* __restrict__ qh,
                 const float* __restrict__ kh,
                 const float* __restrict__ vh,
                 const float* __restrict__ rpb,
                 float* __restrict__ out)
{
    const int bi0  = blockIdx.x * 4;
    const int h    = threadIdx.x >> 5;
    const int lane = threadIdx.x & 31;
    const int qi   = lane >> 3;
    const int d8   = (lane & 7) * 8;

    const int bi = bi0 + qi;
    const int i  = bi & (LL - 1);

    int start = i - RR;
    if (start < 0) start = 0;
    if (start > LL - KK) start = LL - KK;

    const size_t qoff = (size_t)bi * CC + h * DH + d8;
    float4 qa = *reinterpret_cast<const float4*>(qh + qoff);
    float4 qb = *reinterpret_cast<const float4*>(qh + qoff + 4);
    qa.x *= SCALE; qa.y *= SCALE; qa.z *= SCALE; qa.w *= SCALE;
    qb.x *= SCALE; qb.y *= SCALE; qb.z *= SCALE; qb.w *= SCALE;

    const size_t nbase = (size_t)(bi - i + start) * CC + h * DH + d8;
    const int bias_off = h * NBIAS + (start - i + (KK - 1));

    float s[KK];
#pragma unroll
    for (int k = 0; k < KK; k++) {
        const float* kp = kh + nbase + (size_t)k * CC;
        const float4 ka = *reinterpret_cast<const float4*>(kp);
        const float4 kb = *reinterpret_cast<const float4*>(kp + 4);
        float d = qa.x * ka.x + qa.y * ka.y + qa.z * ka.z + qa.w * ka.w
                + qb.x * kb.x + qb.y * kb.y + qb.z * kb.z + qb.w * kb.w;
        d += __shfl_xor_sync(0xffffffffu, d, 1);
        d += __shfl_xor_sync(0xffffffffu, d, 2);
        d += __shfl_xor_sync(0xffffffffu, d, 4);
        s[k] = d + rpb[bias_off + k];
    }

    float m = s[0];
#pragma unroll
    for (int k = 1; k < KK; k++) m = fmaxf(m, s[k]);
    float sum = 0.0f;
#pragma unroll
    for (int k = 0; k < KK; k++) { s[k] = __expf(s[k] - m); sum += s[k]; }
    const float inv = 1.0f / sum;

    float4 oa = make_float4(0.f, 0.f, 0.f, 0.f);
    float4 ob = make_float4(0.f, 0.f, 0.f, 0.f);
#pragma unroll
    for (int k = 0; k < KK; k++) {
        const float* vp = vh + nbase + (size_t)k * CC;
        const float4 va = *reinterpret_cast<const float4*>(vp);
        const float4 vb = *reinterpret_cast<const float4*>(vp + 4);
        const float p = s[k] * inv;
        oa.x = fmaf(p, va.x, oa.x); oa.y = fmaf(p, va.y, oa.y);
        oa.z = fmaf(p, va.z, oa.z); oa.w = fmaf(p, va.w, oa.w);
        ob.x = fmaf(p, vb.x, ob.x); ob.y = fmaf(p, vb.y, ob.y);
        ob.z = fmaf(p, vb.z, ob.z); ob.w = fmaf(p, vb.w, ob.w);
    }

    float4 ra, rb;
    ra.x = __uint_as_float(f2tf32(oa.x)); ra.y = __uint_as_float(f2tf32(oa.y));
    ra.z = __uint_as_float(f2tf32(oa.z)); ra.w = __uint_as_float(f2tf32(oa.w));
    rb.x = __uint_as_float(f2tf32(ob.x)); rb.y = __uint_as_float(f2tf32(ob.y));
    rb.z = __uint_as_float(f2tf32(ob.z)); rb.w = __uint_as_float(f2tf32(ob.w));
    *reinterpret_cast<float4*>(out + qoff)     = ra;
    *reinterpret_cast<float4*>(out + qoff + 4) = rb;
}

// ---------------------------------------------------------------------------
// Launch. Inputs: q, k, v, Wq, bq, Wk, bk, Wv, bv, rpb, Wo, bo
// ---------------------------------------------------------------------------
extern "C" void kernel_launch(void* const* d_in, const int* in_sizes, int n_in,
                              void* d_out, int out_size)
{
    const float* q   = (const float*)d_in[0];
    const float* k   = (const float*)d_in[1];
    const float* v   = (const float*)d_in[2];
    const float* Wq  = (const float*)d_in[3];
    const float* bq  = (const float*)d_in[4];
    const float* Wk  = (const float*)d_in[5];
    const float* bk  = (const float*)d_in[6];
    const float* Wv  = (const float*)d_in[7];
    const float* bv  = (const float*)d_in[8];
    const float* rpb = (const float*)d_in[9];
    const float* Wo  = (const float*)d_in[10];
    const float* bo  = (const float*)d_in[11];
    float* out = (float*)d_out;

    float *qh, *kh, *vh, *att, *rw;
    cudaGetSymbolAddress((void**)&qh,  g_qh);
    cudaGetSymbolAddress((void**)&kh,  g_kh);
    cudaGetSymbolAddress((void**)&vh,  g_vh);
    cudaGetSymbolAddress((void**)&att, g_att);
    cudaGetSymbolAddress((void**)&rw,  g_rw);

    const int smem_bytes = SMEM_FLOATS * 4;   // 107520 B
    cudaFuncSetAttribute(tf32_gemm_qkv,
                         cudaFuncAttributeMaxDynamicSharedMemorySize, smem_bytes);
    cudaFuncSetAttribute(tf32_gemm_out,
                         cudaFuncAttributeMaxDynamicSharedMemorySize, smem_bytes);

    // One launch rounds all 4 weight matrices into g_rw[0..3]
    dim3 rgrid(CC * CC / 1024, 4);
    round_tf32_all<<<rgrid, 256>>>(Wq, Wk, Wv, Wo, rw);

    dim3 qkv_grid(CC / 128, M_TOTAL / 128, 3);   // (4, 64, 3)
    tf32_gemm_qkv<<<qkv_grid, 512, smem_bytes>>>(q, k, v, rw,
                                                 bq, bk, bv, qh, kh, vh);

    natt_kernel<<<M_TOTAL / 4, 256>>>(qh, kh, vh, rpb, att);

    dim3 gemm_grid(CC / 128, M_TOTAL / 128);     // (4, 64)
    tf32_gemm_out<<<gemm_grid, 512, smem_bytes>>>(att, rw + 3 * CC * CC, bo, out);
}

// round 10
// speedup vs baseline: 1.4000x; 1.3599x over previous
#include <cuda_runtime.h>
#include <cuda_fp16.h>
#include <cstdint>

// Problem constants
#define BB 2
#define LL 4096
#define CC 512
#define HH 8
#define KK 13
#define DH 64
#define RR 6              // K/2
#define NBIAS 25          // 2K-1
#define SCALE 0.125f      // DH^-0.5

#define M_TOTAL (BB * LL)   // 8192 rows per GEMM

// GEMM tiling: 128x128 tile, BK=32, 3-stage cp.async, 256 threads (8 warps 2x4)
#define BKD 32
#define A_STRIDE_F 40       // floats/row; 160B (16B-aligned)
#define B_STRIDE_H 40       // halfs/row; 80B (16B-aligned); bank 20g+t conflict-free
#define STAGES 3
#define A_STAGE_F (128 * A_STRIDE_F)   // 5120 floats (20480 B)
#define B_STAGE_H (128 * B_STRIDE_H)   // 5120 halfs  (10240 B)
#define STAGE_BYTES (A_STAGE_F * 4 + B_STAGE_H * 2)   // 30720
#define SMEM_BYTES (STAGES * STAGE_BYTES)             // 92160

// ---------------------------------------------------------------------------
// Scratch (no cudaMalloc allowed).
// NOTE: g_wt MUST be 16B-aligned — it is the GLOBAL SOURCE of cp.async.cg 16B
// copies; __half's natural 2B alignment is not guaranteed sufficient.
// ---------------------------------------------------------------------------
__device__ __align__(16) float  g_qh[M_TOTAL * CC];
__device__ __align__(16) float  g_kh[M_TOTAL * CC];
__device__ __align__(16) float  g_vh[M_TOTAL * CC];
__device__ __align__(16) float  g_att[M_TOTAL * CC];
__device__ __align__(16) __half g_wt[4][CC * CC];   // fp16 weights, transposed [N][K]

// ---------------------------------------------------------------------------
// Helpers
// ---------------------------------------------------------------------------
__device__ __forceinline__ uint32_t pack_h2(float lo, float hi) {
    __half2 h = __floats2half2_rn(lo, hi);   // .x = lo (low 16 bits)
    return *reinterpret_cast<uint32_t*>(&h);
}

__device__ __forceinline__ void mma_f16(float& c0, float& c1, float& c2, float& c3,
                                        uint32_t a0, uint32_t a1, uint32_t a2, uint32_t a3,
                                        uint32_t b0, uint32_t b1) {
    asm volatile(
        "mma.sync.aligned.m16n8k16.row.col.f32.f16.f16.f32 "
        "{%0,%1,%2,%3}, {%4,%5,%6,%7}, {%8,%9}, {%0,%1,%2,%3};"
        : "+f"(c0), "+f"(c1), "+f"(c2), "+f"(c3)
        : "r"(a0), "r"(a1), "r"(a2), "r"(a3), "r"(b0), "r"(b1));
}

__device__ __forceinline__ void cp_async16(uint32_t smem_addr, const void* gptr) {
    asm volatile("cp.async.cg.shared.global [%0], [%1], 16;"
                 :: "r"(smem_addr), "l"(gptr));
}
__device__ __forceinline__ void cp_commit() {
    asm volatile("cp.async.commit_group;");
}
template <int N>
__device__ __forceinline__ void cp_wait() {
    asm volatile("cp.async.wait_group %0;" :: "n"(N));
}

// ---------------------------------------------------------------------------
// Weight transpose + fp16 round, ALL FOUR weights in one launch.
// Wt[z][n][k] = half(W_z[k][n])
// ---------------------------------------------------------------------------
__global__ void transpose_half_all(const float* __restrict__ w0, const float* __restrict__ w1,
                                   const float* __restrict__ w2, const float* __restrict__ w3,
                                   __half* __restrict__ out)
{
    const float* W = (blockIdx.z == 0) ? w0 : (blockIdx.z == 1) ? w1
                   : (blockIdx.z == 2) ? w2 : w3;
    __half* dst = out + (size_t)blockIdx.z * CC * CC;

    __shared__ float t[32][33];
    int x = blockIdx.x * 32 + threadIdx.x;   // n
    int y = blockIdx.y * 32 + threadIdx.y;   // k
#pragma unroll
    for (int i = 0; i < 32; i += 8)
        t[threadIdx.y + i][threadIdx.x] = W[(size_t)(y + i) * CC + x];
    __syncthreads();
    x = blockIdx.y * 32 + threadIdx.x;       // k
    y = blockIdx.x * 32 + threadIdx.y;       // n
#pragma unroll
    for (int i = 0; i < 32; i += 8)
        dst[(size_t)(y + i) * CC + x] = __float2half_rn(t[threadIdx.x][threadIdx.y + i]);
}

// ---------------------------------------------------------------------------
// FP16 tensor-core GEMM body. C[M,512] = A[M,512] @ Wt^T + bias
// A fp32 in smem (cp.async), cvt to half2 at fragment load.
// B fp16 [N][K] in smem (cp.async raw).
// 256 threads, 8 warps (2x4), warp tile 64x32, BK=32, 3-stage.
// ---------------------------------------------------------------------------
__device__ __forceinline__
void gemm_body(const float* __restrict__ A,
               const __half* __restrict__ Wt,
               const float* __restrict__ bias,
               float* __restrict__ C)
{
    extern __shared__ float smem[];
    float*  As = smem;                                  // [STAGES][A_STAGE_F]
    __half* Bs = reinterpret_cast<__half*>(smem + STAGES * A_STAGE_F);

    const uint32_t as_base = (uint32_t)__cvta_generic_to_shared(As);
    const uint32_t bs_base = (uint32_t)__cvta_generic_to_shared(Bs);

    const int tid  = threadIdx.x;
    const int warp = tid >> 5;
    const int lane = tid & 31;
    const int g = lane >> 2;          // 0..7
    const int t = lane & 3;           // 0..3
    const int wm = (warp & 1) * 64;
    const int wn = (warp >> 1) * 32;
    const int block_row = blockIdx.y * 128;
    const int block_col = blockIdx.x * 128;

    const float*  Abase = A  + (size_t)block_row * CC;
    const __half* Bbase = Wt + (size_t)block_col * CC;

    const int NT = CC / BKD;   // 16 K-chunks

    // Per-chunk copy: A = 128 rows x 32 f32 = 1024 cp16; B = 128 rows x 32 h = 512 cp16
    auto issue_tile = [&](int it, int stg) {
        const float*  An = Abase + it * BKD;
        const __half* Bn = Bbase + it * BKD;
        const uint32_t a_off = as_base + (uint32_t)stg * (A_STAGE_F * 4u);
        const uint32_t b_off = bs_base + (uint32_t)stg * (B_STAGE_H * 2u);
#pragma unroll
        for (int i = 0; i < 4; i++) {
            const int idx = tid + i * 256;
            const int arow = idx >> 3, akq = (idx & 7) * 4;     // 0..127, {0,4,..,28}
            cp_async16(a_off + (uint32_t)(arow * A_STRIDE_F + akq) * 4u,
                       An + (size_t)arow * CC + akq);
        }
#pragma unroll
        for (int i = 0; i < 2; i++) {
            const int idx = tid + i * 256;
            const int brow = idx >> 2, bkq = (idx & 3) * 8;     // 0..127, {0,8,16,24}
            cp_async16(b_off + (uint32_t)(brow * B_STRIDE_H + bkq) * 2u,
                       Bn + (size_t)brow * CC + bkq);
        }
        cp_commit();
    };

    float acc[4][4][4];
#pragma unroll
    for (int mi = 0; mi < 4; mi++)
#pragma unroll
        for (int ni = 0; ni < 4; ni++)
#pragma unroll
            for (int r = 0; r < 4; r++) acc[mi][ni][r] = 0.0f;

    issue_tile(0, 0);
    issue_tile(1, 1);
    cp_wait<1>();
    __syncthreads();

    int cur = 0;
    for (int it = 0; it < NT; ++it) {
        if (it + 2 < NT) issue_tile(it + 2, (cur + 2) % STAGES);

        const float* asf = As + cur * A_STAGE_F;
        const uint32_t* bsu = reinterpret_cast<const uint32_t*>(Bs + cur * B_STAGE_H);
#pragma unroll
        for (int k0 = 0; k0 < BKD; k0 += 16) {   // 2 k-steps of K=16
            const int k0h = k0 >> 1;             // u32 index offset into B
            uint32_t ar[4][4], br[4][2];
#pragma unroll
            for (int mi = 0; mi < 4; mi++) {
                const int r0 = (wm + mi * 16 + g) * A_STRIDE_F;
                const int r8 = r0 + 8 * A_STRIDE_F;
                const float2 v0 = *reinterpret_cast<const float2*>(asf + r0 + k0 + 2 * t);
                const float2 v1 = *reinterpret_cast<const float2*>(asf + r8 + k0 + 2 * t);
                const float2 v2 = *reinterpret_cast<const float2*>(asf + r0 + k0 + 2 * t + 8);
                const float2 v3 = *reinterpret_cast<const float2*>(asf + r8 + k0 + 2 * t + 8);
                ar[mi][0] = pack_h2(v0.x, v0.y);
                ar[mi][1] = pack_h2(v1.x, v1.y);
                ar[mi][2] = pack_h2(v2.x, v2.y);
                ar[mi][3] = pack_h2(v3.x, v3.y);
            }
#pragma unroll
            for (int ni = 0; ni < 4; ni++) {
                const int n20 = (wn + ni * 8 + g) * (B_STRIDE_H / 2);
                br[ni][0] = bsu[n20 + k0h + t];
                br[ni][1] = bsu[n20 + k0h + t + 4];
            }
#pragma unroll
            for (int mi = 0; mi < 4; mi++)
#pragma unroll
                for (int ni = 0; ni < 4; ni++)
                    mma_f16(acc[mi][ni][0], acc[mi][ni][1], acc[mi][ni][2], acc[mi][ni][3],
                            ar[mi][0], ar[mi][1], ar[mi][2], ar[mi][3],
                            br[ni][0], br[ni][1]);
        }

        cp_wait<1>();
        __syncthreads();
        cur = (cur + 1) % STAGES;
    }

    // Epilogue: c0,c1 = (row g, cols 2t,2t+1); c2,c3 = row g+8
#pragma unroll
    for (int mi = 0; mi < 4; mi++) {
        const int row0 = block_row + wm + mi * 16 + g;
#pragma unroll
        for (int ni = 0; ni < 4; ni++) {
            const int col0 = block_col + wn + ni * 8 + t * 2;
            const float2 b2 = *reinterpret_cast<const float2*>(bias + col0);
            float2 o;
            o.x = acc[mi][ni][0] + b2.x;
            o.y = acc[mi][ni][1] + b2.y;
            *reinterpret_cast<float2*>(C + (size_t)row0 * CC + col0) = o;
            o.x = acc[mi][ni][2] + b2.x;
            o.y = acc[mi][ni][3] + b2.y;
            *reinterpret_cast<float2*>(C + (size_t)(row0 + 8) * CC + col0) = o;
        }
    }
}

// Batched QKV: blockIdx.z selects (A, W, bias, C)
__global__ __launch_bounds__(256, 2)
void hgemm_qkv(const float* __restrict__ q, const float* __restrict__ k,
               const float* __restrict__ v,
               const __half* __restrict__ wt,
               const float* __restrict__ bq, const float* __restrict__ bk,
               const float* __restrict__ bv,
               float* __restrict__ qh, float* __restrict__ kh,
               float* __restrict__ vh)
{
    const int z = blockIdx.z;
    const float*  A    = (z == 0) ? q  : (z == 1) ? k  : v;
    const __half* W    = wt + (size_t)z * CC * CC;
    const float*  bias = (z == 0) ? bq : (z == 1) ? bk : bv;
    float*        C    = (z == 0) ? qh : (z == 1) ? kh : vh;
    gemm_body(A, W, bias, C);
}

__global__ __launch_bounds__(256, 2)
void hgemm_out(const float* __restrict__ A, const __half* __restrict__ W,
               const float* __restrict__ bias, float* __restrict__ C)
{
    gemm_body(A, W, bias, C);
}

// ---------------------------------------------------------------------------
// Neighborhood attention, vectorized.
// Lane layout: qi = lane>>3 (4 queries/warp), d8 = (lane&7)*8.
// ---------------------------------------------------------------------------
__global__ __launch_bounds__(256)
void natt_kernel(const float* __restrict__ qh,
                 const float* __restrict__ kh,
                 const float* __restrict__ vh,
                 const float* __restrict__ rpb,
                 float* __restrict__ out)
{
    const int bi0  = blockIdx.x * 4;
    const int h    = threadIdx.x >> 5;
    const int lane = threadIdx.x & 31;
    const int qi   = lane >> 3;
    const int d8   = (lane & 7) * 8;

    const int bi = bi0 + qi;
    const int i  = bi & (LL - 1);

    int start = i - RR;
    if (start < 0) start = 0;
    if (start > LL - KK) start = LL - KK;

    const size_t qoff = (size_t)bi * CC + h * DH + d8;
    float4 qa = *reinterpret_cast<const float4*>(qh + qoff);
    float4 qb = *reinterpret_cast<const float4*>(qh + qoff + 4);
    qa.x *= SCALE; qa.y *= SCALE; qa.z *= SCALE; qa.w *= SCALE;
    qb.x *= SCALE; qb.y *= SCALE; qb.z *= SCALE; qb.w *= SCALE;

    const size_t nbase = (size_t)(bi - i + start) * CC + h * DH + d8;
    const int bias_off = h * NBIAS + (start - i + (KK - 1));

    float s[KK];
#pragma unroll
    for (int k = 0; k < KK; k++) {
        const float* kp = kh + nbase + (size_t)k * CC;
        const float4 ka = *reinterpret_cast<const float4*>(kp);
        const float4 kb = *reinterpret_cast<const float4*>(kp + 4);
        float d = qa.x * ka.x + qa.y * ka.y + qa.z * ka.z + qa.w * ka.w
                + qb.x * kb.x + qb.y * kb.y + qb.z * kb.z + qb.w * kb.w;
        d += __shfl_xor_sync(0xffffffffu, d, 1);
        d += __shfl_xor_sync(0xffffffffu, d, 2);
        d += __shfl_xor_sync(0xffffffffu, d, 4);
        s[k] = d + rpb[bias_off + k];
    }

    float m = s[0];
#pragma unroll
    for (int k = 1; k < KK; k++) m = fmaxf(m, s[k]);
    float sum = 0.0f;
#pragma unroll
    for (int k = 0; k < KK; k++) { s[k] = __expf(s[k] - m); sum += s[k]; }
    const float inv = 1.0f / sum;

    float4 oa = make_float4(0.f, 0.f, 0.f, 0.f);
    float4 ob = make_float4(0.f, 0.f, 0.f, 0.f);
#pragma unroll
    for (int k = 0; k < KK; k++) {
        const float* vp = vh + nbase + (size_t)k * CC;
        const float4 va = *reinterpret_cast<const float4*>(vp);
        const float4 vb = *reinterpret_cast<const float4*>(vp + 4);
        const float p = s[k] * inv;
        oa.x = fmaf(p, va.x, oa.x); oa.y = fmaf(p, va.y, oa.y);
        oa.z = fmaf(p, va.z, oa.z); oa.w = fmaf(p, va.w, oa.w);
        ob.x = fmaf(p, vb.x, ob.x); ob.y = fmaf(p, vb.y, ob.y);
        ob.z = fmaf(p, vb.z, ob.z); ob.w = fmaf(p, vb.w, ob.w);
    }

    *reinterpret_cast<float4*>(out + qoff)     = oa;
    *reinterpret_cast<float4*>(out + qoff + 4) = ob;
}

// ---------------------------------------------------------------------------
// Launch. Inputs: q, k, v, Wq, bq, Wk, bk, Wv, bv, rpb, Wo, bo
// ---------------------------------------------------------------------------
extern "C" void kernel_launch(void* const* d_in, const int* in_sizes, int n_in,
                              void* d_out, int out_size)
{
    const float* q   = (const float*)d_in[0];
    const float* k   = (const float*)d_in[1];
    const float* v   = (const float*)d_in[2];
    const float* Wq  = (const float*)d_in[3];
    const float* bq  = (const float*)d_in[4];
    const float* Wk  = (const float*)d_in[5];
    const float* bk  = (const float*)d_in[6];
    const float* Wv  = (const float*)d_in[7];
    const float* bv  = (const float*)d_in[8];
    const float* rpb = (const float*)d_in[9];
    const float* Wo  = (const float*)d_in[10];
    const float* bo  = (const float*)d_in[11];
    float* out = (float*)d_out;

    float *qh, *kh, *vh, *att;
    __half* wt;
    cudaGetSymbolAddress((void**)&qh,  g_qh);
    cudaGetSymbolAddress((void**)&kh,  g_kh);
    cudaGetSymbolAddress((void**)&vh,  g_vh);
    cudaGetSymbolAddress((void**)&att, g_att);
    cudaGetSymbolAddress((void**)&wt,  g_wt);

    cudaFuncSetAttribute(hgemm_qkv,
                         cudaFuncAttributeMaxDynamicSharedMemorySize, SMEM_BYTES);
    cudaFuncSetAttribute(hgemm_out,
                         cudaFuncAttributeMaxDynamicSharedMemorySize, SMEM_BYTES);

    // One launch: transpose + fp16-round all 4 weights
    dim3 tblk(32, 8), tgrid(CC / 32, CC / 32, 4);
    transpose_half_all<<<tgrid, tblk>>>(Wq, Wk, Wv, Wo, wt);

    dim3 qkv_grid(CC / 128, M_TOTAL / 128, 3);   // (4, 64, 3)
    hgemm_qkv<<<qkv_grid, 256, SMEM_BYTES>>>(q, k, v, wt, bq, bk, bv, qh, kh, vh);

    natt_kernel<<<M_TOTAL / 4, 256>>>(qh, kh, vh, rpb, att);

    dim3 gemm_grid(CC / 128, M_TOTAL / 128);     // (4, 64)
    hgemm_out<<<gemm_grid, 256, SMEM_BYTES>>>(att, wt + 3 * CC * CC, bo, out);
}

// round 11
// speedup vs baseline: 1.6740x; 1.1957x over previous
#include <cuda_runtime.h>
#include <cuda_fp16.h>
#include <cstdint>

// Problem constants
#define BB 2
#define LL 4096
#define CC 512
#define HH 8
#define KK 13
#define DH 64
#define RR 6              // K/2
#define NBIAS 25          // 2K-1
#define SCALE 0.125f      // DH^-0.5

#define M_TOTAL (BB * LL)   // 8192 rows per GEMM

// GEMM tiling: 128x128 tile, BK=32, 3-stage cp.async, 256 threads (8 warps 2x4)
#define BKD 32
#define A_STRIDE_F 40       // fp32 A: floats/row; 160B
#define A_STRIDE_H 40       // fp16 A: halfs/row; 80B; bank 20g+t conflict-free
#define B_STRIDE_H 40       // fp16 B: halfs/row; 80B; bank 20g+t conflict-free
#define STAGES 3
#define A_STAGE_F (128 * A_STRIDE_F)   // 5120 floats (20480 B)
#define A_STAGE_H (128 * A_STRIDE_H)   // 5120 halfs  (10240 B)
#define B_STAGE_H (128 * B_STRIDE_H)   // 5120 halfs  (10240 B)
#define SMEM_BYTES_F32A (STAGES * (A_STAGE_F * 4 + B_STAGE_H * 2))  // 92160
#define SMEM_BYTES_F16A (STAGES * (A_STAGE_H * 2 + B_STAGE_H * 2))  // 61440

// ---------------------------------------------------------------------------
// Scratch (no cudaMalloc). All cp.async global sources MUST be 16B-aligned.
// ---------------------------------------------------------------------------
__device__ __align__(16) __half g_qh[M_TOTAL * CC];
__device__ __align__(16) __half g_kh[M_TOTAL * CC];
__device__ __align__(16) __half g_vh[M_TOTAL * CC];
__device__ __align__(16) __half g_att[M_TOTAL * CC];
__device__ __align__(16) __half g_wt[4][CC * CC];   // fp16 weights, transposed [N][K]

// ---------------------------------------------------------------------------
// Helpers
// ---------------------------------------------------------------------------
__device__ __forceinline__ uint32_t pack_h2(float lo, float hi) {
    __half2 h = __floats2half2_rn(lo, hi);
    return *reinterpret_cast<uint32_t*>(&h);
}

__device__ __forceinline__ void mma_f16(float& c0, float& c1, float& c2, float& c3,
                                        uint32_t a0, uint32_t a1, uint32_t a2, uint32_t a3,
                                        uint32_t b0, uint32_t b1) {
    asm volatile(
        "mma.sync.aligned.m16n8k16.row.col.f32.f16.f16.f32 "
        "{%0,%1,%2,%3}, {%4,%5,%6,%7}, {%8,%9}, {%0,%1,%2,%3};"
        : "+f"(c0), "+f"(c1), "+f"(c2), "+f"(c3)
        : "r"(a0), "r"(a1), "r"(a2), "r"(a3), "r"(b0), "r"(b1));
}

__device__ __forceinline__ void cp_async16(uint32_t smem_addr, const void* gptr) {
    asm volatile("cp.async.cg.shared.global [%0], [%1], 16;"
                 :: "r"(smem_addr), "l"(gptr));
}
__device__ __forceinline__ void cp_commit() {
    asm volatile("cp.async.commit_group;");
}
template <int N>
__device__ __forceinline__ void cp_wait() {
    asm volatile("cp.async.wait_group %0;" :: "n"(N));
}

// ---------------------------------------------------------------------------
// Weight transpose + fp16 round, all four weights in one launch.
// ---------------------------------------------------------------------------
__global__ void transpose_half_all(const float* __restrict__ w0, const float* __restrict__ w1,
                                   const float* __restrict__ w2, const float* __restrict__ w3,
                                   __half* __restrict__ out)
{
    const float* W = (blockIdx.z == 0) ? w0 : (blockIdx.z == 1) ? w1
                   : (blockIdx.z == 2) ? w2 : w3;
    __half* dst = out + (size_t)blockIdx.z * CC * CC;

    __shared__ float t[32][33];
    int x = blockIdx.x * 32 + threadIdx.x;
    int y = blockIdx.y * 32 + threadIdx.y;
#pragma unroll
    for (int i = 0; i < 32; i += 8)
        t[threadIdx.y + i][threadIdx.x] = W[(size_t)(y + i) * CC + x];
    __syncthreads();
    x = blockIdx.y * 32 + threadIdx.x;
    y = blockIdx.x * 32 + threadIdx.y;
#pragma unroll
    for (int i = 0; i < 32; i += 8)
        dst[(size_t)(y + i) * CC + x] = __float2half_rn(t[threadIdx.x][threadIdx.y + i]);
}

// ---------------------------------------------------------------------------
// FP16 tensor-core GEMM body. C[M,512] = A[M,512] @ Wt^T + bias
// A_HALF: A is fp16 [M][K] (raw u32 fragment loads), else fp32 (cvt at load).
// OutT: __half (round at store) or float.
// ---------------------------------------------------------------------------
template <bool A_HALF, class OutT>
__device__ __forceinline__
void gemm_body(const void* __restrict__ Araw,
               const __half* __restrict__ Wt,
               const float* __restrict__ bias,
               OutT* __restrict__ C)
{
    extern __shared__ char smem_raw[];
    float*  AsF = reinterpret_cast<float*>(smem_raw);
    __half* AsH = reinterpret_cast<__half*>(smem_raw);
    __half* Bs  = A_HALF
        ? reinterpret_cast<__half*>(smem_raw + STAGES * A_STAGE_H * 2)
        : reinterpret_cast<__half*>(smem_raw + STAGES * A_STAGE_F * 4);

    const uint32_t as_base = (uint32_t)__cvta_generic_to_shared(smem_raw);
    const uint32_t bs_base = (uint32_t)__cvta_generic_to_shared(Bs);

    const int tid  = threadIdx.x;
    const int warp = tid >> 5;
    const int lane = tid & 31;
    const int g = lane >> 2;
    const int t = lane & 3;
    const int wm = (warp & 1) * 64;
    const int wn = (warp >> 1) * 32;
    const int block_row = blockIdx.y * 128;
    const int block_col = blockIdx.x * 128;

    const float*  AbF = reinterpret_cast<const float*>(Araw)  + (size_t)block_row * CC;
    const __half* AbH = reinterpret_cast<const __half*>(Araw) + (size_t)block_row * CC;
    const __half* Bbase = Wt + (size_t)block_col * CC;

    const int NT = CC / BKD;   // 16 K-chunks

    auto issue_tile = [&](int it, int stg) {
        const __half* Bn = Bbase + it * BKD;
        const uint32_t b_off = bs_base + (uint32_t)stg * (B_STAGE_H * 2u);
        if (A_HALF) {
            const __half* An = AbH + it * BKD;
            const uint32_t a_off = as_base + (uint32_t)stg * (A_STAGE_H * 2u);
#pragma unroll
            for (int i = 0; i < 2; i++) {
                const int idx = tid + i * 256;
                const int arow = idx >> 2, akq = (idx & 3) * 8;
                cp_async16(a_off + (uint32_t)(arow * A_STRIDE_H + akq) * 2u,
                           An + (size_t)arow * CC + akq);
            }
        } else {
            const float* An = AbF + it * BKD;
            const uint32_t a_off = as_base + (uint32_t)stg * (A_STAGE_F * 4u);
#pragma unroll
            for (int i = 0; i < 4; i++) {
                const int idx = tid + i * 256;
                const int arow = idx >> 3, akq = (idx & 7) * 4;
                cp_async16(a_off + (uint32_t)(arow * A_STRIDE_F + akq) * 4u,
                           An + (size_t)arow * CC + akq);
            }
        }
#pragma unroll
        for (int i = 0; i < 2; i++) {
            const int idx = tid + i * 256;
            const int brow = idx >> 2, bkq = (idx & 3) * 8;
            cp_async16(b_off + (uint32_t)(brow * B_STRIDE_H + bkq) * 2u,
                       Bn + (size_t)brow * CC + bkq);
        }
        cp_commit();
    };

    float acc[4][4][4];
#pragma unroll
    for (int mi = 0; mi < 4; mi++)
#pragma unroll
        for (int ni = 0; ni < 4; ni++)
#pragma unroll
            for (int r = 0; r < 4; r++) acc[mi][ni][r] = 0.0f;

    issue_tile(0, 0);
    issue_tile(1, 1);
    cp_wait<1>();
    __syncthreads();

    int cur = 0;
    for (int it = 0; it < NT; ++it) {
        if (it + 2 < NT) issue_tile(it + 2, (cur + 2) % STAGES);

        const float*    asf = AsF + cur * A_STAGE_F;
        const uint32_t* asu = reinterpret_cast<const uint32_t*>(AsH + cur * A_STAGE_H);
        const uint32_t* bsu = reinterpret_cast<const uint32_t*>(Bs  + cur * B_STAGE_H);
#pragma unroll
        for (int k0 = 0; k0 < BKD; k0 += 16) {
            const int k0h = k0 >> 1;
            uint32_t ar[4][4], br[4][2];
#pragma unroll
            for (int mi = 0; mi < 4; mi++) {
                if (A_HALF) {
                    const int r0 = (wm + mi * 16 + g) * (A_STRIDE_H / 2);
                    const int r8 = r0 + 8 * (A_STRIDE_H / 2);
                    ar[mi][0] = asu[r0 + k0h + t];
                    ar[mi][1] = asu[r8 + k0h + t];
                    ar[mi][2] = asu[r0 + k0h + t + 4];
                    ar[mi][3] = asu[r8 + k0h + t + 4];
                } else {
                    const int r0 = (wm + mi * 16 + g) * A_STRIDE_F;
                    const int r8 = r0 + 8 * A_STRIDE_F;
                    const float2 v0 = *reinterpret_cast<const float2*>(asf + r0 + k0 + 2 * t);
                    const float2 v1 = *reinterpret_cast<const float2*>(asf + r8 + k0 + 2 * t);
                    const float2 v2 = *reinterpret_cast<const float2*>(asf + r0 + k0 + 2 * t + 8);
                    const float2 v3 = *reinterpret_cast<const float2*>(asf + r8 + k0 + 2 * t + 8);
                    ar[mi][0] = pack_h2(v0.x, v0.y);
                    ar[mi][1] = pack_h2(v1.x, v1.y);
                    ar[mi][2] = pack_h2(v2.x, v2.y);
                    ar[mi][3] = pack_h2(v3.x, v3.y);
                }
            }
#pragma unroll
            for (int ni = 0; ni < 4; ni++) {
                const int n20 = (wn + ni * 8 + g) * (B_STRIDE_H / 2);
                br[ni][0] = bsu[n20 + k0h + t];
                br[ni][1] = bsu[n20 + k0h + t + 4];
            }
#pragma unroll
            for (int mi = 0; mi < 4; mi++)
#pragma unroll
                for (int ni = 0; ni < 4; ni++)
                    mma_f16(acc[mi][ni][0], acc[mi][ni][1], acc[mi][ni][2], acc[mi][ni][3],
                            ar[mi][0], ar[mi][1], ar[mi][2], ar[mi][3],
                            br[ni][0], br[ni][1]);
        }

        cp_wait<1>();
        __syncthreads();
        cur = (cur + 1) % STAGES;
    }

    // Epilogue
#pragma unroll
    for (int mi = 0; mi < 4; mi++) {
        const int row0 = block_row + wm + mi * 16 + g;
#pragma unroll
        for (int ni = 0; ni < 4; ni++) {
            const int col0 = block_col + wn + ni * 8 + t * 2;
            const float2 b2 = *reinterpret_cast<const float2*>(bias + col0);
            const float x0 = acc[mi][ni][0] + b2.x;
            const float y0 = acc[mi][ni][1] + b2.y;
            const float x1 = acc[mi][ni][2] + b2.x;
            const float y1 = acc[mi][ni][3] + b2.y;
            if (sizeof(OutT) == 2) {
                __half2* p0 = reinterpret_cast<__half2*>(
                    reinterpret_cast<__half*>(C) + (size_t)row0 * CC + col0);
                __half2* p1 = reinterpret_cast<__half2*>(
                    reinterpret_cast<__half*>(C) + (size_t)(row0 + 8) * CC + col0);
                *p0 = __floats2half2_rn(x0, y0);
                *p1 = __floats2half2_rn(x1, y1);
            } else {
                float* p0 = reinterpret_cast<float*>(C) + (size_t)row0 * CC + col0;
                float* p1 = reinterpret_cast<float*>(C) + (size_t)(row0 + 8) * CC + col0;
                *reinterpret_cast<float2*>(p0) = make_float2(x0, y0);
                *reinterpret_cast<float2*>(p1) = make_float2(x1, y1);
            }
        }
    }
}

// QKV: A fp32, out fp16; blockIdx.z selects triple
__global__ __launch_bounds__(256, 2)
void hgemm_qkv(const float* __restrict__ q, const float* __restrict__ k,
               const float* __restrict__ v,
               const __half* __restrict__ wt,
               const float* __restrict__ bq, const float* __restrict__ bk,
               const float* __restrict__ bv,
               __half* __restrict__ qh, __half* __restrict__ kh,
               __half* __restrict__ vh)
{
    const int z = blockIdx.z;
    const float*  A    = (z == 0) ? q  : (z == 1) ? k  : v;
    const __half* W    = wt + (size_t)z * CC * CC;
    const float*  bias = (z == 0) ? bq : (z == 1) ? bk : bv;
    __half*       C    = (z == 0) ? qh : (z == 1) ? kh : vh;
    gemm_body<false, __half>(A, W, bias, C);
}

// Output GEMM: A fp16 (att), out fp32
__global__ __launch_bounds__(256, 2)
void hgemm_out(const __half* __restrict__ A, const __half* __restrict__ W,
               const float* __restrict__ bias, float* __restrict__ C)
{
    gemm_body<true, float>(A, W, bias, C);
}

// ---------------------------------------------------------------------------
// Neighborhood attention on fp16 tensors, fp32 math, fp16 output.
// Lane layout: qi = lane>>3 (4 queries/warp), d8 = (lane&7)*8.
// ---------------------------------------------------------------------------
__device__ __forceinline__ void ld8h(const __half* p, float* f) {
    const uint4 u = *reinterpret_cast<const uint4*>(p);
    const __half2* h = reinterpret_cast<const __half2*>(&u);
#pragma unroll
    for (int i = 0; i < 4; i++) {
        const float2 v = __half22float2(h[i]);
        f[2 * i] = v.x; f[2 * i + 1] = v.y;
    }
}

__global__ __launch_bounds__(256)
void natt_kernel(const __half* __restrict__ qh,
                 const __half* __restrict__ kh,
                 const __half* __restrict__ vh,
                 const float* __restrict__ rpb,
                 __half* __restrict__ out)
{
    const int bi0  = blockIdx.x * 4;
    const int h    = threadIdx.x >> 5;
    const int lane = threadIdx.x & 31;
    const int qi   = lane >> 3;
    const int d8   = (lane & 7) * 8;

    const int bi = bi0 + qi;
    const int i  = bi & (LL - 1);

    int start = i - RR;
    if (start < 0) start = 0;
    if (start > LL - KK) start = LL - KK;

    const size_t qoff = (size_t)bi * CC + h * DH + d8;
    float qv[8];
    ld8h(qh + qoff, qv);
#pragma unroll
    for (int d = 0; d < 8; d++) qv[d] *= SCALE;

    const size_t nbase = (size_t)(bi - i + start) * CC + h * DH + d8;
    const int bias_off = h * NBIAS + (start - i + (KK - 1));

    float s[KK];
#pragma unroll
    for (int k = 0; k < KK; k++) {
        float kv[8];
        ld8h(kh + nbase + (size_t)k * CC, kv);
        float d = qv[0] * kv[0];
#pragma unroll
        for (int dd = 1; dd < 8; dd++) d = fmaf(qv[dd], kv[dd], d);
        d += __shfl_xor_sync(0xffffffffu, d, 1);
        d += __shfl_xor_sync(0xffffffffu, d, 2);
        d += __shfl_xor_sync(0xffffffffu, d, 4);
        s[k] = d + rpb[bias_off + k];
    }

    float m = s[0];
#pragma unroll
    for (int k = 1; k < KK; k++) m = fmaxf(m, s[k]);
    float sum = 0.0f;
#pragma unroll
    for (int k = 0; k < KK; k++) { s[k] = __expf(s[k] - m); sum += s[k]; }
    const float inv = 1.0f / sum;

    float o[8] = {0.f, 0.f, 0.f, 0.f, 0.f, 0.f, 0.f, 0.f};
#pragma unroll
    for (int k = 0; k < KK; k++) {
        float vv[8];
        ld8h(vh + nbase + (size_t)k * CC, vv);
        const float p = s[k] * inv;
#pragma unroll
        for (int dd = 0; dd < 8; dd++) o[dd] = fmaf(p, vv[dd], o[dd]);
    }

    uint4 u;
    __half2* hp = reinterpret_cast<__half2*>(&u);
#pragma unroll
    for (int ii = 0; ii < 4; ii++)
        hp[ii] = __floats2half2_rn(o[2 * ii], o[2 * ii + 1]);
    *reinterpret_cast<uint4*>(out + qoff) = u;
}

// ---------------------------------------------------------------------------
// Launch. Inputs: q, k, v, Wq, bq, Wk, bk, Wv, bv, rpb, Wo, bo
// ---------------------------------------------------------------------------
extern "C" void kernel_launch(void* const* d_in, const int* in_sizes, int n_in,
                              void* d_out, int out_size)
{
    const float* q   = (const float*)d_in[0];
    const float* k   = (const float*)d_in[1];
    const float* v   = (const float*)d_in[2];
    const float* Wq  = (const float*)d_in[3];
    const float* bq  = (const float*)d_in[4];
    const float* Wk  = (const float*)d_in[5];
    const float* bk  = (const float*)d_in[6];
    const float* Wv  = (const float*)d_in[7];
    const float* bv  = (const float*)d_in[8];
    const float* rpb = (const float*)d_in[9];
    const float* Wo  = (const float*)d_in[10];
    const float* bo  = (const float*)d_in[11];
    float* out = (float*)d_out;

    __half *qh, *kh, *vh, *att, *wt;
    cudaGetSymbolAddress((void**)&qh,  g_qh);
    cudaGetSymbolAddress((void**)&kh,  g_kh);
    cudaGetSymbolAddress((void**)&vh,  g_vh);
    cudaGetSymbolAddress((void**)&att, g_att);
    cudaGetSymbolAddress((void**)&wt,  g_wt);

    cudaFuncSetAttribute(hgemm_qkv,
                         cudaFuncAttributeMaxDynamicSharedMemorySize, SMEM_BYTES_F32A);
    cudaFuncSetAttribute(hgemm_out,
                         cudaFuncAttributeMaxDynamicSharedMemorySize, SMEM_BYTES_F16A);

    dim3 tblk(32, 8), tgrid(CC / 32, CC / 32, 4);
    transpose_half_all<<<tgrid, tblk>>>(Wq, Wk, Wv, Wo, wt);

    dim3 qkv_grid(CC / 128, M_TOTAL / 128, 3);
    hgemm_qkv<<<qkv_grid, 256, SMEM_BYTES_F32A>>>(q, k, v, wt, bq, bk, bv, qh, kh, vh);

    natt_kernel<<<M_TOTAL / 4, 256>>>(qh, kh, vh, rpb, att);

    dim3 gemm_grid(CC / 128, M_TOTAL / 128);
    hgemm_out<<<gemm_grid, 256, SMEM_BYTES_F16A>>>(att, wt + 3 * CC * CC, bo, out);
}